// round 8
// baseline (speedup 1.0000x reference)
#include <cuda_runtime.h>

typedef unsigned long long u64;

#define BATCH 8
#define NCH   19
#define HH    512
#define WW    512
#define NWORDS 8                 // 512 cols / 64 bits
#define IMG_WORDS (HH*NWORDS)    // 4096 words per image

// Scratch (device globals — no allocation)
__device__ u64   g_imgp8[BATCH*HH*WW/8];              // 2 MB, u8 pixels packed
__device__ u64   g_strong[2][BATCH*IMG_WORDS];
__device__ u64   g_weak  [2][BATCH*IMG_WORDS];
__device__ u64   g_edges [2][BATCH*IMG_WORDS];
__device__ float g_loss;
__device__ unsigned g_count;

// ---------------------------------------------------------------------------
// Kernel 1: per-pixel argmax over 19 channels -> img_p = (cls*255)%256 as u8
// 8 pixels (2 float4) per thread; one u64 store.
// ---------------------------------------------------------------------------
__global__ __launch_bounds__(256) void argmax_kernel(const float* __restrict__ pred) {
    const int Q = (HH*WW)/4;                 // 65536 float4 per channel plane
    int i = blockIdx.x*256 + threadIdx.x;    // 8*Q/2 threads
    int j = 2*i;
    int b = j / Q;
    int p = j - b*Q;
    const float4* base = reinterpret_cast<const float4*>(pred) + (size_t)b*NCH*Q + p;
    float4 best0 = base[0];
    float4 best1 = base[1];
    int i0x=0,i0y=0,i0z=0,i0w=0, i1x=0,i1y=0,i1z=0,i1w=0;
    #pragma unroll
    for (int c = 1; c < NCH; ++c) {
        float4 v0 = base[(size_t)c*Q];
        float4 v1 = base[(size_t)c*Q + 1];
        if (v0.x > best0.x) { best0.x = v0.x; i0x = c; }
        if (v0.y > best0.y) { best0.y = v0.y; i0y = c; }
        if (v0.z > best0.z) { best0.z = v0.z; i0z = c; }
        if (v0.w > best0.w) { best0.w = v0.w; i0w = c; }
        if (v1.x > best1.x) { best1.x = v1.x; i1x = c; }
        if (v1.y > best1.y) { best1.y = v1.y; i1y = c; }
        if (v1.z > best1.z) { best1.z = v1.z; i1z = c; }
        if (v1.w > best1.w) { best1.w = v1.w; i1w = c; }
    }
    // (cls*255)%256 = cls ? 256-cls : 0, all fit in u8
    u64 w = 0;
    w |= (u64)(unsigned char)(i0x ? 256 - i0x : 0);
    w |= (u64)(unsigned char)(i0y ? 256 - i0y : 0) << 8;
    w |= (u64)(unsigned char)(i0z ? 256 - i0z : 0) << 16;
    w |= (u64)(unsigned char)(i0w ? 256 - i0w : 0) << 24;
    w |= (u64)(unsigned char)(i1x ? 256 - i1x : 0) << 32;
    w |= (u64)(unsigned char)(i1y ? 256 - i1y : 0) << 40;
    w |= (u64)(unsigned char)(i1z ? 256 - i1z : 0) << 48;
    w |= (u64)(unsigned char)(i1w ? 256 - i1w : 0) << 56;
    g_imgp8[i] = w;
}

// ---------------------------------------------------------------------------
// Kernel 2: Canny frontend for BOTH images in one launch (z: 0-7 pred, 8-15 lbl)
// One CTA per 64x64 tile. Outputs bitpacked strong/weak masks.
// ---------------------------------------------------------------------------
__device__ __forceinline__ int binof(float gx, float gy) {
    // Exact quantization of atan2 angle mod 180 into {0:d0, 1:d45, 2:d90, 3:d135}
    if (gy == 0.0f) return 0;        // includes gx==0,gy==0 -> angle 0
    if (gx == 0.0f) return 2;        // +-90 deg
    float ax = fabsf(gx), ay = fabsf(gy);
    const float T1 = 0.41421356237309503f;   // tan(22.5) = sqrt(2)-1
    if (ay < T1*ax) return 0;                // |angle| < 22.5
    if (T1*ay < ax)                           // < 67.5  (tan67.5 = 1/T1)
        return ((gx > 0.0f) == (gy > 0.0f)) ? 1 : 3;
    return 2;
}

__global__ __launch_bounds__(256) void canny_front(const float* __restrict__ labels) {
    __shared__ float simg[68][72];           // img tile with halo 2 (edge-clamped)
    __shared__ float smag[66][72];           // mag tile with halo 1 (0 outside image)
    __shared__ unsigned char sbin[64][64];
    const int tx0 = blockIdx.x*64, ty0 = blockIdx.y*64;
    const int sel = blockIdx.z >> 3, b = blockIdx.z & 7;
    const int t = threadIdx.x;
    const unsigned char* ip8 =
        reinterpret_cast<const unsigned char*>(g_imgp8) + (size_t)b*HH*WW;
    const float* ipf = labels + (size_t)b*HH*WW;
    // load img tile (edge padding via clamp)
    for (int i = t; i < 68*68; i += 256) {
        int r = i/68, c = i - r*68;
        int gy = ty0 + r - 2; gy = gy < 0 ? 0 : (gy > HH-1 ? HH-1 : gy);
        int gx = tx0 + c - 2; gx = gx < 0 ? 0 : (gx > WW-1 ? WW-1 : gx);
        float v = (sel == 0) ? (float)ip8[gy*WW + gx]
                             : floorf(ipf[gy*WW + gx] * 255.0f);
        simg[r][c] = v;
    }
    __syncthreads();
    // mag (+bin for centers); mag = 0 outside the image (zero-padded mp)
    for (int i = t; i < 66*66; i += 256) {
        int r = i/66, c = i - r*66;          // mag at tile-local (r-1, c-1)
        int gy = ty0 + r - 1, gx = tx0 + c - 1;
        float m = 0.0f;
        if ((unsigned)gy < (unsigned)HH && (unsigned)gx < (unsigned)WW) {
            float a00=simg[r][c],   a01=simg[r][c+1],   a02=simg[r][c+2];
            float a10=simg[r+1][c],                     a12=simg[r+1][c+2];
            float a20=simg[r+2][c], a21=simg[r+2][c+1], a22=simg[r+2][c+2];
            float gxv = (a02 - a00) + 2.0f*(a12 - a10) + (a22 - a20);
            float gyv = (a20 - a00) + 2.0f*(a21 - a01) + (a22 - a02);
            m = fabsf(gxv) + fabsf(gyv);     // exact integer in fp32
            if (r >= 1 && r < 65 && c >= 1 && c < 65)
                sbin[r-1][c-1] = (unsigned char)binof(gxv, gyv);
        }
        smag[r][c] = m;
    }
    __syncthreads();
    // NMS + thresholds, ballot-packed into u64 rows (lane l -> bits l and l+32)
    const int warp = t >> 5, lane = t & 31;
    for (int r = warp; r < 64; r += 8) {
        bool sb[2], wb[2];
        #pragma unroll
        for (int half = 0; half < 2; ++half) {
            int px = lane + half*32;
            float m = smag[r+1][px+1];
            int bn = sbin[r][px];
            float n1, n2;
            if      (bn == 0) { n1 = smag[r+1][px+2]; n2 = smag[r+1][px];   }
            else if (bn == 1) { n1 = smag[r][px+2];   n2 = smag[r+2][px];   }
            else if (bn == 2) { n1 = smag[r+2][px+1]; n2 = smag[r][px+1];   }
            else              { n1 = smag[r][px];     n2 = smag[r+2][px+2]; }
            bool keep = (m >= n1) && (m >= n2);
            sb[half] = keep && (m > 200.0f);
            wb[half] = keep && (m > 100.0f);
        }
        unsigned slo = __ballot_sync(0xffffffffu, sb[0]);
        unsigned shi = __ballot_sync(0xffffffffu, sb[1]);
        unsigned wlo = __ballot_sync(0xffffffffu, wb[0]);
        unsigned whi = __ballot_sync(0xffffffffu, wb[1]);
        if (lane == 0) {
            size_t w = ((size_t)b*HH + (ty0 + r))*NWORDS + blockIdx.x;
            g_strong[sel][w] = (u64)slo | ((u64)shi << 32);
            g_weak  [sel][w] = (u64)wlo | ((u64)whi << 32);
        }
    }
}

// ---------------------------------------------------------------------------
// Kernel 3: hysteresis to fixed point (cap 256), whole image in smem, bitpacked
// grid = 16 CTAs (2 images x 8 batch), 512 threads, 64KB dynamic smem
// Also resets the loss accumulator for this call (runs before loss kernel).
// ---------------------------------------------------------------------------
__global__ __launch_bounds__(512) void hyst_kernel() {
    if (blockIdx.x == 0 && threadIdx.x == 0) { g_loss = 0.0f; g_count = 0u; }
    extern __shared__ u64 sh[];
    u64* s  = sh;              // 4096 words: current state
    u64* hd = sh + IMG_WORDS;  // 4096 words: horizontal dilation
    const int img = blockIdx.x >> 3;
    const int b   = blockIdx.x & 7;
    const u64* wbase = g_weak[img]   + (size_t)b*IMG_WORDS;
    const u64* sbase = g_strong[img] + (size_t)b*IMG_WORDS;
    const int t = threadIdx.x;
    u64 wr[8];
    #pragma unroll
    for (int k = 0; k < 8; ++k) {
        int idx = t + 512*k;
        wr[k] = wbase[idx];
        s[idx] = sbase[idx];
    }
    __syncthreads();
    bool changed = true;
    for (int it = 0; it < 256 && changed; ++it) {
        #pragma unroll
        for (int k = 0; k < 8; ++k) {
            int idx = t + 512*k;
            int wc = idx & 7;
            u64 x = s[idx];
            u64 l = wc       ? s[idx-1] : 0ull;
            u64 r = (wc < 7) ? s[idx+1] : 0ull;
            hd[idx] = x | (x << 1) | (x >> 1) | (l >> 63) | (r << 63);
        }
        __syncthreads();
        int my = 0;
        #pragma unroll
        for (int k = 0; k < 8; ++k) {
            int idx = t + 512*k;
            int h = idx >> 3;
            u64 v = hd[idx];
            if (h > 0)      v |= hd[idx - 8];
            if (h < HH-1)   v |= hd[idx + 8];
            v &= wr[k];
            my |= (int)(v != s[idx]);
            s[idx] = v;
        }
        changed = (__syncthreads_or(my) != 0);
    }
    #pragma unroll
    for (int k = 0; k < 8; ++k) {
        int idx = t + 512*k;
        g_edges[img][(size_t)b*IMG_WORDS + idx] = s[idx];
    }
}

// ---------------------------------------------------------------------------
// Kernel 4: closed-form loss. Per (b,w) column over H:
//   n1p = sum ep, S_el = sum el, S_both = sum ep&el
//   loss = [ sum_col S_el*log(512 + n1p*(e-1)) - sum ep&el (flat popcount) ]/4096
// One CTA per (batch, word-column), 1024 threads. Staging threads (t<512) load
// both column words and popcount ep&el. Extraction: thread = (bit=t>>4,
// chunk=t&15), rows h = chunk + 16*i  -> conflict-free broadcast LDS.
// ---------------------------------------------------------------------------
__global__ __launch_bounds__(1024) void loss_kernel(float* __restrict__ out) {
    __shared__ u64 sep[HH];     // pred edge column words
    __shared__ u64 slb[HH];     // label edge column words
    __shared__ int ssb[16];     // per-warp popc(ep&el) partials
    const int b  = blockIdx.x >> 3;
    const int wc = blockIdx.x & 7;
    const int t  = threadIdx.x;
    const u64* __restrict__ ep = g_edges[0] + (size_t)b*IMG_WORDS + wc;
    const u64* __restrict__ el = g_edges[1] + (size_t)b*IMG_WORDS + wc;
    // stage + flat popcount of ep&el (S_both needs no per-column structure)
    int sb = 0;
    if (t < 512) {
        u64 A = __ldg(ep + (size_t)t*NWORDS);
        u64 B = __ldg(el + (size_t)t*NWORDS);
        sep[t] = A;
        slb[t] = B;
        sb = __popcll(A & B);
        #pragma unroll
        for (int o = 16; o; o >>= 1) sb += __shfl_down_sync(0xffffffffu, sb, o);
        if ((t & 31) == 0) ssb[t >> 5] = sb;
    }
    __syncthreads();
    const int bit   = t >> 4;    // 0..63
    const int chunk = t & 15;    // strided row subset
    int n1p = 0, selc = 0;
    #pragma unroll
    for (int i = 0; i < 32; ++i) {
        int h = chunk + 16*i;    // lanes 0-15 hit 16 consecutive u64s: no conflicts
        n1p  += (int)((sep[h] >> bit) & 1ull);
        selc += (int)((slb[h] >> bit) & 1ull);
    }
    // combine 16 row-chunks of the same bit (adjacent lanes)
    #pragma unroll
    for (int o = 8; o; o >>= 1) {
        n1p  += __shfl_down_sync(0xffffffffu, n1p,  o, 16);
        selc += __shfl_down_sync(0xffffffffu, selc, o, 16);
    }
    float val = 0.0f;
    if (chunk == 0) {
        const float EM1 = 1.7182818284590452f;    // e - 1
        float lse = logf(512.0f + (float)n1p * EM1);
        val = (float)selc * lse;
    }
    // warp + block reduce, one atomic per block
    #pragma unroll
    for (int o = 16; o; o >>= 1) val += __shfl_down_sync(0xffffffffu, val, o);
    __shared__ float wsum[32];
    if ((t & 31) == 0) wsum[t >> 5] = val;
    __syncthreads();
    if (t < 32) {
        float v = wsum[t];
        #pragma unroll
        for (int o = 16; o; o >>= 1) v += __shfl_down_sync(0xffffffffu, v, o);
        if (t == 0) {
            int stot = 0;
            #pragma unroll
            for (int i = 0; i < 16; ++i) stot += ssb[i];
            atomicAdd(&g_loss, (v - (float)stot) * (1.0f/4096.0f));
        }
    }
    // last block finalizes the scalar output
    if (t == 0) {
        __threadfence();
        unsigned prev = atomicAdd(&g_count, 1u);
        if (prev == gridDim.x - 1) {
            out[0] = atomicAdd(&g_loss, 0.0f);  // atomic read: coherent with adds
        }
    }
}

// ---------------------------------------------------------------------------
extern "C" void kernel_launch(void* const* d_in, const int* in_sizes, int n_in,
                              void* d_out, int out_size) {
    const float* pred   = (const float*)d_in[0];
    const float* labels = (const float*)d_in[1];
    // defensive: identify by size (pred has 19x more elements)
    if (n_in >= 2 && in_sizes[0] == BATCH*HH*WW) {
        const float* tmp = pred; pred = labels; labels = tmp;
    }
    argmax_kernel<<<(BATCH*((HH*WW)/4)/2)/256, 256>>>(pred);
    dim3 g(WW/64, HH/64, 2*BATCH);
    canny_front<<<g, 256>>>(labels);
    cudaFuncSetAttribute(hyst_kernel, cudaFuncAttributeMaxDynamicSharedMemorySize,
                         2*IMG_WORDS*(int)sizeof(u64));
    hyst_kernel<<<16, 512, 2*IMG_WORDS*sizeof(u64)>>>();
    loss_kernel<<<64, 1024>>>((float*)d_out);
}

// round 9
// speedup vs baseline: 1.2753x; 1.2753x over previous
#include <cuda_runtime.h>

typedef unsigned long long u64;

#define BATCH 8
#define NCH   19
#define HH    512
#define WW    512
#define NWORDS 8                 // 512 cols / 64 bits
#define IMG_WORDS (HH*NWORDS)    // 4096 words per image

// Scratch (device globals — no allocation)
__device__ u64   g_imgp8[BATCH*HH*WW/8];              // 2 MB, u8 pixels packed
__device__ u64   g_strong[2][BATCH*IMG_WORDS];
__device__ u64   g_weak  [2][BATCH*IMG_WORDS];
// TRANSPOSED edge layout: word index = wc*HH + h  (column-major word storage)
__device__ u64   g_edges [2][BATCH*IMG_WORDS];
__device__ float g_loss;
__device__ unsigned g_count;

// ---------------------------------------------------------------------------
// Kernel 1: per-pixel argmax over 19 channels -> img_p = (cls*255)%256 as u8
// 8 pixels (2 float4) per thread; one u64 store. Also resets loss accumulators.
// ---------------------------------------------------------------------------
__global__ __launch_bounds__(256) void argmax_kernel(const float* __restrict__ pred) {
    if (blockIdx.x == 0 && threadIdx.x == 0) { g_loss = 0.0f; g_count = 0u; }
    const int Q = (HH*WW)/4;                 // 65536 float4 per channel plane
    int i = blockIdx.x*256 + threadIdx.x;    // 8*Q/2 threads
    int j = 2*i;
    int b = j / Q;
    int p = j - b*Q;
    const float4* base = reinterpret_cast<const float4*>(pred) + (size_t)b*NCH*Q + p;
    float4 best0 = base[0];
    float4 best1 = base[1];
    int i0x=0,i0y=0,i0z=0,i0w=0, i1x=0,i1y=0,i1z=0,i1w=0;
    #pragma unroll
    for (int c = 1; c < NCH; ++c) {
        float4 v0 = base[(size_t)c*Q];
        float4 v1 = base[(size_t)c*Q + 1];
        if (v0.x > best0.x) { best0.x = v0.x; i0x = c; }
        if (v0.y > best0.y) { best0.y = v0.y; i0y = c; }
        if (v0.z > best0.z) { best0.z = v0.z; i0z = c; }
        if (v0.w > best0.w) { best0.w = v0.w; i0w = c; }
        if (v1.x > best1.x) { best1.x = v1.x; i1x = c; }
        if (v1.y > best1.y) { best1.y = v1.y; i1y = c; }
        if (v1.z > best1.z) { best1.z = v1.z; i1z = c; }
        if (v1.w > best1.w) { best1.w = v1.w; i1w = c; }
    }
    // (cls*255)%256 = cls ? 256-cls : 0, all fit in u8
    u64 w = 0;
    w |= (u64)(unsigned char)(i0x ? 256 - i0x : 0);
    w |= (u64)(unsigned char)(i0y ? 256 - i0y : 0) << 8;
    w |= (u64)(unsigned char)(i0z ? 256 - i0z : 0) << 16;
    w |= (u64)(unsigned char)(i0w ? 256 - i0w : 0) << 24;
    w |= (u64)(unsigned char)(i1x ? 256 - i1x : 0) << 32;
    w |= (u64)(unsigned char)(i1y ? 256 - i1y : 0) << 40;
    w |= (u64)(unsigned char)(i1z ? 256 - i1z : 0) << 48;
    w |= (u64)(unsigned char)(i1w ? 256 - i1w : 0) << 56;
    g_imgp8[i] = w;
}

// ---------------------------------------------------------------------------
// Kernel 2: Canny frontend, one image set per launch (SEL template param).
// One CTA per 64x64 tile. Outputs bitpacked strong/weak masks.
// ---------------------------------------------------------------------------
__device__ __forceinline__ int binof(float gx, float gy) {
    // Exact quantization of atan2 angle mod 180 into {0:d0, 1:d45, 2:d90, 3:d135}
    if (gy == 0.0f) return 0;        // includes gx==0,gy==0 -> angle 0
    if (gx == 0.0f) return 2;        // +-90 deg
    float ax = fabsf(gx), ay = fabsf(gy);
    const float T1 = 0.41421356237309503f;   // tan(22.5) = sqrt(2)-1
    if (ay < T1*ax) return 0;                // |angle| < 22.5
    if (T1*ay < ax)                           // < 67.5  (tan67.5 = 1/T1)
        return ((gx > 0.0f) == (gy > 0.0f)) ? 1 : 3;
    return 2;
}

template<int SEL>
__global__ __launch_bounds__(256) void canny_front(const float* __restrict__ labels) {
    __shared__ float simg[68][72];           // img tile with halo 2 (edge-clamped)
    __shared__ float smag[66][72];           // mag tile with halo 1 (0 outside image)
    __shared__ unsigned char sbin[64][64];
    const int tx0 = blockIdx.x*64, ty0 = blockIdx.y*64;
    const int b = blockIdx.z;
    const int t = threadIdx.x;
    const unsigned char* ip8 =
        reinterpret_cast<const unsigned char*>(g_imgp8) + (size_t)b*HH*WW;
    const float* ipf = labels + (size_t)b*HH*WW;
    // load img tile (edge padding via clamp)
    for (int i = t; i < 68*68; i += 256) {
        int r = i/68, c = i - r*68;
        int gy = ty0 + r - 2; gy = gy < 0 ? 0 : (gy > HH-1 ? HH-1 : gy);
        int gx = tx0 + c - 2; gx = gx < 0 ? 0 : (gx > WW-1 ? WW-1 : gx);
        float v = (SEL == 0) ? (float)ip8[gy*WW + gx]
                             : floorf(ipf[gy*WW + gx] * 255.0f);
        simg[r][c] = v;
    }
    __syncthreads();
    // mag (+bin for centers); mag = 0 outside the image (zero-padded mp)
    for (int i = t; i < 66*66; i += 256) {
        int r = i/66, c = i - r*66;          // mag at tile-local (r-1, c-1)
        int gy = ty0 + r - 1, gx = tx0 + c - 1;
        float m = 0.0f;
        if ((unsigned)gy < (unsigned)HH && (unsigned)gx < (unsigned)WW) {
            float a00=simg[r][c],   a01=simg[r][c+1],   a02=simg[r][c+2];
            float a10=simg[r+1][c],                     a12=simg[r+1][c+2];
            float a20=simg[r+2][c], a21=simg[r+2][c+1], a22=simg[r+2][c+2];
            float gxv = (a02 - a00) + 2.0f*(a12 - a10) + (a22 - a20);
            float gyv = (a20 - a00) + 2.0f*(a21 - a01) + (a22 - a02);
            m = fabsf(gxv) + fabsf(gyv);     // exact integer in fp32
            if (r >= 1 && r < 65 && c >= 1 && c < 65)
                sbin[r-1][c-1] = (unsigned char)binof(gxv, gyv);
        }
        smag[r][c] = m;
    }
    __syncthreads();
    // NMS + thresholds, ballot-packed into u64 rows (lane l -> bits l and l+32)
    const int warp = t >> 5, lane = t & 31;
    for (int r = warp; r < 64; r += 8) {
        bool sb[2], wb[2];
        #pragma unroll
        for (int half = 0; half < 2; ++half) {
            int px = lane + half*32;
            float m = smag[r+1][px+1];
            int bn = sbin[r][px];
            float n1, n2;
            if      (bn == 0) { n1 = smag[r+1][px+2]; n2 = smag[r+1][px];   }
            else if (bn == 1) { n1 = smag[r][px+2];   n2 = smag[r+2][px];   }
            else if (bn == 2) { n1 = smag[r+2][px+1]; n2 = smag[r][px+1];   }
            else              { n1 = smag[r][px];     n2 = smag[r+2][px+2]; }
            bool keep = (m >= n1) && (m >= n2);
            sb[half] = keep && (m > 200.0f);
            wb[half] = keep && (m > 100.0f);
        }
        unsigned slo = __ballot_sync(0xffffffffu, sb[0]);
        unsigned shi = __ballot_sync(0xffffffffu, sb[1]);
        unsigned wlo = __ballot_sync(0xffffffffu, wb[0]);
        unsigned whi = __ballot_sync(0xffffffffu, wb[1]);
        if (lane == 0) {
            size_t w = ((size_t)b*HH + (ty0 + r))*NWORDS + blockIdx.x;
            g_strong[SEL][w] = (u64)slo | ((u64)shi << 32);
            g_weak  [SEL][w] = (u64)wlo | ((u64)whi << 32);
        }
    }
}

// ---------------------------------------------------------------------------
// Kernel 3: hysteresis to fixed point (cap 256), whole image in smem, bitpacked
// One image set per launch (IMG template param), grid = 8 CTAs, 512 threads.
// Final edges stored TRANSPOSED: word index wc*HH + h (coalesced loss staging).
// ---------------------------------------------------------------------------
template<int IMG>
__global__ __launch_bounds__(512) void hyst_kernel() {
    extern __shared__ u64 sh[];
    u64* s  = sh;              // 4096 words: current state
    u64* hd = sh + IMG_WORDS;  // 4096 words: horizontal dilation
    const int b = blockIdx.x;
    const u64* wbase = g_weak[IMG]   + (size_t)b*IMG_WORDS;
    const u64* sbase = g_strong[IMG] + (size_t)b*IMG_WORDS;
    const int t = threadIdx.x;
    u64 wr[8];
    #pragma unroll
    for (int k = 0; k < 8; ++k) {
        int idx = t + 512*k;
        wr[k] = wbase[idx];
        s[idx] = sbase[idx];
    }
    __syncthreads();
    bool changed = true;
    for (int it = 0; it < 256 && changed; ++it) {
        #pragma unroll
        for (int k = 0; k < 8; ++k) {
            int idx = t + 512*k;
            int wc = idx & 7;
            u64 x = s[idx];
            u64 l = wc       ? s[idx-1] : 0ull;
            u64 r = (wc < 7) ? s[idx+1] : 0ull;
            hd[idx] = x | (x << 1) | (x >> 1) | (l >> 63) | (r << 63);
        }
        __syncthreads();
        int my = 0;
        #pragma unroll
        for (int k = 0; k < 8; ++k) {
            int idx = t + 512*k;
            int h = idx >> 3;
            u64 v = hd[idx];
            if (h > 0)      v |= hd[idx - 8];
            if (h < HH-1)   v |= hd[idx + 8];
            v &= wr[k];
            my |= (int)(v != s[idx]);
            s[idx] = v;
        }
        changed = (__syncthreads_or(my) != 0);
    }
    // store transposed: (h, wc) -> wc*HH + h
    #pragma unroll
    for (int k = 0; k < 8; ++k) {
        int idx = t + 512*k;
        int h = idx >> 3, wc = idx & 7;
        g_edges[IMG][(size_t)b*IMG_WORDS + wc*HH + h] = s[idx];
    }
}

// ---------------------------------------------------------------------------
// Kernel 4: closed-form loss. Per (b,w) column over H:
//   n1p = sum ep, S_el = sum el; S_both via flat popcount.
//   loss = [ sum_col S_el*log(512 + n1p*(e-1)) - sum popc(ep&el) ]/4096
// One CTA per (batch, word-column), 1024 threads. Staging now fully coalesced
// (transposed edges). Extraction: thread = (bit=t>>4, chunk=t&15), rows
// h = chunk + 16*i -> conflict-free broadcast LDS.
// ---------------------------------------------------------------------------
__global__ __launch_bounds__(1024) void loss_kernel(float* __restrict__ out) {
    __shared__ u64 sep[HH];     // pred edge column words
    __shared__ u64 slb[HH];     // label edge column words
    __shared__ int ssb[16];     // per-warp popc(ep&el) partials
    const int b  = blockIdx.x >> 3;
    const int wc = blockIdx.x & 7;
    const int t  = threadIdx.x;
    const u64* __restrict__ ep = g_edges[0] + (size_t)b*IMG_WORDS + wc*HH;
    const u64* __restrict__ el = g_edges[1] + (size_t)b*IMG_WORDS + wc*HH;
    // stage (coalesced) + flat popcount of ep&el
    int sb = 0;
    if (t < 512) {
        u64 A = __ldg(ep + t);
        u64 B = __ldg(el + t);
        sep[t] = A;
        slb[t] = B;
        sb = __popcll(A & B);
        #pragma unroll
        for (int o = 16; o; o >>= 1) sb += __shfl_down_sync(0xffffffffu, sb, o);
        if ((t & 31) == 0) ssb[t >> 5] = sb;
    }
    __syncthreads();
    const int bit   = t >> 4;    // 0..63
    const int chunk = t & 15;    // strided row subset
    int n1p = 0, selc = 0;
    #pragma unroll
    for (int i = 0; i < 32; ++i) {
        int h = chunk + 16*i;    // lanes 0-15 hit 16 consecutive u64s: no conflicts
        n1p  += (int)((sep[h] >> bit) & 1ull);
        selc += (int)((slb[h] >> bit) & 1ull);
    }
    // combine 16 row-chunks of the same bit (adjacent lanes)
    #pragma unroll
    for (int o = 8; o; o >>= 1) {
        n1p  += __shfl_down_sync(0xffffffffu, n1p,  o, 16);
        selc += __shfl_down_sync(0xffffffffu, selc, o, 16);
    }
    float val = 0.0f;
    if (chunk == 0) {
        const float EM1 = 1.7182818284590452f;    // e - 1
        float lse = logf(512.0f + (float)n1p * EM1);
        val = (float)selc * lse;
    }
    // warp + block reduce, one atomic per block
    #pragma unroll
    for (int o = 16; o; o >>= 1) val += __shfl_down_sync(0xffffffffu, val, o);
    __shared__ float wsum[32];
    if ((t & 31) == 0) wsum[t >> 5] = val;
    __syncthreads();
    if (t < 32) {
        float v = wsum[t];
        #pragma unroll
        for (int o = 16; o; o >>= 1) v += __shfl_down_sync(0xffffffffu, v, o);
        if (t == 0) {
            int stot = 0;
            #pragma unroll
            for (int i = 0; i < 16; ++i) stot += ssb[i];
            atomicAdd(&g_loss, (v - (float)stot) * (1.0f/4096.0f));
        }
    }
    // last block finalizes the scalar output
    if (t == 0) {
        __threadfence();
        unsigned prev = atomicAdd(&g_count, 1u);
        if (prev == gridDim.x - 1) {
            out[0] = atomicAdd(&g_loss, 0.0f);  // atomic read: coherent with adds
        }
    }
}

// ---------------------------------------------------------------------------
extern "C" void kernel_launch(void* const* d_in, const int* in_sizes, int n_in,
                              void* d_out, int out_size) {
    const float* pred   = (const float*)d_in[0];
    const float* labels = (const float*)d_in[1];
    // defensive: identify by size (pred has 19x more elements)
    if (n_in >= 2 && in_sizes[0] == BATCH*HH*WW) {
        const float* tmp = pred; pred = labels; labels = tmp;
    }

    // one-time host-side setup (streams/events are host objects, not device mem)
    static cudaStream_t s2 = nullptr;
    static cudaEvent_t evFork = nullptr, evJoin = nullptr;
    static bool smem_set = false;
    if (!s2) {
        cudaStreamCreateWithFlags(&s2, cudaStreamNonBlocking);
        cudaEventCreateWithFlags(&evFork, cudaEventDisableTiming);
        cudaEventCreateWithFlags(&evJoin, cudaEventDisableTiming);
    }
    if (!smem_set) {
        cudaFuncSetAttribute(hyst_kernel<0>, cudaFuncAttributeMaxDynamicSharedMemorySize,
                             2*IMG_WORDS*(int)sizeof(u64));
        cudaFuncSetAttribute(hyst_kernel<1>, cudaFuncAttributeMaxDynamicSharedMemorySize,
                             2*IMG_WORDS*(int)sizeof(u64));
        smem_set = true;
    }

    dim3 g(WW/64, HH/64, BATCH);

    // fork: label pipeline on s2 (independent of argmax)
    cudaEventRecord(evFork, 0);
    cudaStreamWaitEvent(s2, evFork, 0);
    canny_front<1><<<g, 256, 0, s2>>>(labels);
    hyst_kernel<1><<<BATCH, 512, 2*IMG_WORDS*sizeof(u64), s2>>>();
    cudaEventRecord(evJoin, s2);

    // pred pipeline on default stream
    argmax_kernel<<<(BATCH*((HH*WW)/4)/2)/256, 256>>>(pred);
    canny_front<0><<<g, 256>>>(nullptr);
    hyst_kernel<0><<<BATCH, 512, 2*IMG_WORDS*sizeof(u64)>>>();

    // join, then loss
    cudaStreamWaitEvent(0, evJoin, 0);
    loss_kernel<<<64, 1024>>>((float*)d_out);
}

// round 10
// speedup vs baseline: 1.3548x; 1.0624x over previous
#include <cuda_runtime.h>

typedef unsigned long long u64;

#define BATCH 8
#define NCH   19
#define HH    512
#define WW    512
#define NWORDS 8                 // 512 cols / 64 bits
#define IMG_WORDS (HH*NWORDS)    // 4096 words per image

// Scratch (device globals — no allocation)
__device__ u64   g_imgp8[BATCH*HH*WW/8];              // 2 MB, u8 pixels packed
__device__ u64   g_strong[2][BATCH*IMG_WORDS];
__device__ u64   g_weak  [2][BATCH*IMG_WORDS];
// TRANSPOSED edge layout: word index = wc*HH + h  (column-major word storage)
__device__ u64   g_edges [2][BATCH*IMG_WORDS];
__device__ float g_loss;
__device__ unsigned g_count;

// ---------------------------------------------------------------------------
// Kernel 1: per-pixel argmax over 19 channels -> img_p = (cls*255)%256 as u8
// 8 pixels (2 float4) per thread; one u64 store. Also resets loss accumulators.
// ---------------------------------------------------------------------------
__global__ __launch_bounds__(256) void argmax_kernel(const float* __restrict__ pred) {
    if (blockIdx.x == 0 && threadIdx.x == 0) { g_loss = 0.0f; g_count = 0u; }
    const int Q = (HH*WW)/4;                 // 65536 float4 per channel plane
    int i = blockIdx.x*256 + threadIdx.x;    // 8*Q/2 threads
    int j = 2*i;
    int b = j / Q;
    int p = j - b*Q;
    const float4* base = reinterpret_cast<const float4*>(pred) + (size_t)b*NCH*Q + p;
    float4 best0 = base[0];
    float4 best1 = base[1];
    int i0x=0,i0y=0,i0z=0,i0w=0, i1x=0,i1y=0,i1z=0,i1w=0;
    #pragma unroll
    for (int c = 1; c < NCH; ++c) {
        float4 v0 = base[(size_t)c*Q];
        float4 v1 = base[(size_t)c*Q + 1];
        if (v0.x > best0.x) { best0.x = v0.x; i0x = c; }
        if (v0.y > best0.y) { best0.y = v0.y; i0y = c; }
        if (v0.z > best0.z) { best0.z = v0.z; i0z = c; }
        if (v0.w > best0.w) { best0.w = v0.w; i0w = c; }
        if (v1.x > best1.x) { best1.x = v1.x; i1x = c; }
        if (v1.y > best1.y) { best1.y = v1.y; i1y = c; }
        if (v1.z > best1.z) { best1.z = v1.z; i1z = c; }
        if (v1.w > best1.w) { best1.w = v1.w; i1w = c; }
    }
    // (cls*255)%256 = cls ? 256-cls : 0, all fit in u8
    u64 w = 0;
    w |= (u64)(unsigned char)(i0x ? 256 - i0x : 0);
    w |= (u64)(unsigned char)(i0y ? 256 - i0y : 0) << 8;
    w |= (u64)(unsigned char)(i0z ? 256 - i0z : 0) << 16;
    w |= (u64)(unsigned char)(i0w ? 256 - i0w : 0) << 24;
    w |= (u64)(unsigned char)(i1x ? 256 - i1x : 0) << 32;
    w |= (u64)(unsigned char)(i1y ? 256 - i1y : 0) << 40;
    w |= (u64)(unsigned char)(i1z ? 256 - i1z : 0) << 48;
    w |= (u64)(unsigned char)(i1w ? 256 - i1w : 0) << 56;
    g_imgp8[i] = w;
}

// ---------------------------------------------------------------------------
// Kernel 2: Canny frontend, integer pipeline. One CTA per 64x64 tile.
// u8 image tile, int Sobel, u16 magnitude, int NMS/thresholds; only the two
// angle-bin boundary compares are fp32 (exactness proven via Pell bound).
// ---------------------------------------------------------------------------
__device__ __forceinline__ int binof_i(int gx, int gy) {
    // Exact quantization of atan2 angle mod 180 into {0:d0, 1:d45, 2:d90, 3:d135}
    if (gy == 0) return 0;           // includes gx==0,gy==0 -> angle 0
    if (gx == 0) return 2;           // +-90 deg
    int ax = gx < 0 ? -gx : gx, ay = gy < 0 ? -gy : gy;
    float fax = (float)ax, fay = (float)ay;
    const float T1 = 0.41421356237309503f;   // tan(22.5) = sqrt(2)-1
    if (fay < T1*fax) return 0;               // |angle| < 22.5
    if (T1*fay < fax)                          // < 67.5  (tan67.5 = 1/T1)
        return ((gx > 0) == (gy > 0)) ? 1 : 3;
    return 2;
}

template<int SEL>
__global__ __launch_bounds__(256) void canny_front(const float* __restrict__ labels) {
    __shared__ unsigned char  simg[68][72];   // img tile, halo 2 (edge-clamped)
    __shared__ unsigned short smag[66][72];   // mag tile, halo 1 (0 outside image)
    __shared__ unsigned char  sbin[64][64];
    const int tx0 = blockIdx.x*64, ty0 = blockIdx.y*64;
    const int b = blockIdx.z;
    const int t = threadIdx.x;
    const int tx = t & 63, ty = t >> 6;       // 64 x 4 thread layout
    const unsigned char* ip8 =
        reinterpret_cast<const unsigned char*>(g_imgp8) + (size_t)b*HH*WW;
    const float* ipf = labels + (size_t)b*HH*WW;
    // load img tile (edge padding via clamp); no divides
    for (int r = ty; r < 68; r += 4) {
        int gy = ty0 + r - 2; gy = gy < 0 ? 0 : (gy > HH-1 ? HH-1 : gy);
        #pragma unroll
        for (int cc = 0; cc < 2; ++cc) {
            int c = tx + cc*64;
            if (c < 68) {
                int gx = tx0 + c - 2; gx = gx < 0 ? 0 : (gx > WW-1 ? WW-1 : gx);
                unsigned char v;
                if (SEL == 0) v = ip8[gy*WW + gx];
                else          v = (unsigned char)(int)floorf(ipf[gy*WW + gx] * 255.0f);
                simg[r][c] = v;
            }
        }
    }
    __syncthreads();
    // mag (+bin for centers), integer Sobel; mag = 0 outside the image
    for (int r = ty; r < 66; r += 4) {
        int gy = ty0 + r - 1;
        #pragma unroll
        for (int cc = 0; cc < 2; ++cc) {
            int c = tx + cc*64;
            if (c < 66) {
                int gx = tx0 + c - 1;
                int m = 0;
                if ((unsigned)gy < (unsigned)HH && (unsigned)gx < (unsigned)WW) {
                    int a00=simg[r][c],   a01=simg[r][c+1],   a02=simg[r][c+2];
                    int a10=simg[r+1][c],                     a12=simg[r+1][c+2];
                    int a20=simg[r+2][c], a21=simg[r+2][c+1], a22=simg[r+2][c+2];
                    int gxv = (a02 - a00) + 2*(a12 - a10) + (a22 - a20);
                    int gyv = (a20 - a00) + 2*(a21 - a01) + (a22 - a02);
                    int axv = gxv < 0 ? -gxv : gxv;
                    int ayv = gyv < 0 ? -gyv : gyv;
                    m = axv + ayv;                     // <= 2040, fits u16
                    if (r >= 1 && r < 65 && c >= 1 && c < 65)
                        sbin[r-1][c-1] = (unsigned char)binof_i(gxv, gyv);
                }
                smag[r][c] = (unsigned short)m;
            }
        }
    }
    __syncthreads();
    // NMS + thresholds (all int), ballot-packed into u64 rows
    const int warp = t >> 5, lane = t & 31;
    for (int r = warp; r < 64; r += 8) {
        bool sb[2], wb[2];
        #pragma unroll
        for (int half = 0; half < 2; ++half) {
            int px = lane + half*32;
            int m = smag[r+1][px+1];
            int bn = sbin[r][px];
            int n1, n2;
            if      (bn == 0) { n1 = smag[r+1][px+2]; n2 = smag[r+1][px];   }
            else if (bn == 1) { n1 = smag[r][px+2];   n2 = smag[r+2][px];   }
            else if (bn == 2) { n1 = smag[r+2][px+1]; n2 = smag[r][px+1];   }
            else              { n1 = smag[r][px];     n2 = smag[r+2][px+2]; }
            bool keep = (m >= n1) && (m >= n2);
            sb[half] = keep && (m > 200);
            wb[half] = keep && (m > 100);
        }
        unsigned slo = __ballot_sync(0xffffffffu, sb[0]);
        unsigned shi = __ballot_sync(0xffffffffu, sb[1]);
        unsigned wlo = __ballot_sync(0xffffffffu, wb[0]);
        unsigned whi = __ballot_sync(0xffffffffu, wb[1]);
        if (lane == 0) {
            size_t w = ((size_t)b*HH + (ty0 + r))*NWORDS + blockIdx.x;
            g_strong[SEL][w] = (u64)slo | ((u64)shi << 32);
            g_weak  [SEL][w] = (u64)wlo | ((u64)whi << 32);
        }
    }
}

// ---------------------------------------------------------------------------
// Kernel 3: hysteresis to fixed point (cap 256), whole image in smem, bitpacked
// One image set per launch (IMG template param), grid = 8 CTAs, 512 threads.
// Final edges stored TRANSPOSED: word index wc*HH + h (coalesced loss staging).
// ---------------------------------------------------------------------------
template<int IMG>
__global__ __launch_bounds__(512) void hyst_kernel() {
    extern __shared__ u64 sh[];
    u64* s  = sh;              // 4096 words: current state
    u64* hd = sh + IMG_WORDS;  // 4096 words: horizontal dilation
    const int b = blockIdx.x;
    const u64* wbase = g_weak[IMG]   + (size_t)b*IMG_WORDS;
    const u64* sbase = g_strong[IMG] + (size_t)b*IMG_WORDS;
    const int t = threadIdx.x;
    u64 wr[8];
    #pragma unroll
    for (int k = 0; k < 8; ++k) {
        int idx = t + 512*k;
        wr[k] = wbase[idx];
        s[idx] = sbase[idx];
    }
    __syncthreads();
    bool changed = true;
    for (int it = 0; it < 256 && changed; ++it) {
        #pragma unroll
        for (int k = 0; k < 8; ++k) {
            int idx = t + 512*k;
            int wc = idx & 7;
            u64 x = s[idx];
            u64 l = wc       ? s[idx-1] : 0ull;
            u64 r = (wc < 7) ? s[idx+1] : 0ull;
            hd[idx] = x | (x << 1) | (x >> 1) | (l >> 63) | (r << 63);
        }
        __syncthreads();
        int my = 0;
        #pragma unroll
        for (int k = 0; k < 8; ++k) {
            int idx = t + 512*k;
            int h = idx >> 3;
            u64 v = hd[idx];
            if (h > 0)      v |= hd[idx - 8];
            if (h < HH-1)   v |= hd[idx + 8];
            v &= wr[k];
            my |= (int)(v != s[idx]);
            s[idx] = v;
        }
        changed = (__syncthreads_or(my) != 0);
    }
    // store transposed: (h, wc) -> wc*HH + h
    #pragma unroll
    for (int k = 0; k < 8; ++k) {
        int idx = t + 512*k;
        int h = idx >> 3, wc = idx & 7;
        g_edges[IMG][(size_t)b*IMG_WORDS + wc*HH + h] = s[idx];
    }
}

// ---------------------------------------------------------------------------
// Kernel 4: closed-form loss. Per (b,w) column over H:
//   n1p = sum ep, S_el = sum el; S_both via flat popcount.
//   loss = [ sum_col S_el*log(512 + n1p*(e-1)) - sum popc(ep&el) ]/4096
// One CTA per (batch, word-column), 1024 threads. Coalesced staging
// (transposed edges); extraction via conflict-free broadcast LDS.
// ---------------------------------------------------------------------------
__global__ __launch_bounds__(1024) void loss_kernel(float* __restrict__ out) {
    __shared__ u64 sep[HH];     // pred edge column words
    __shared__ u64 slb[HH];     // label edge column words
    __shared__ int ssb[16];     // per-warp popc(ep&el) partials
    const int b  = blockIdx.x >> 3;
    const int wc = blockIdx.x & 7;
    const int t  = threadIdx.x;
    const u64* __restrict__ ep = g_edges[0] + (size_t)b*IMG_WORDS + wc*HH;
    const u64* __restrict__ el = g_edges[1] + (size_t)b*IMG_WORDS + wc*HH;
    // stage (coalesced) + flat popcount of ep&el
    int sb = 0;
    if (t < 512) {
        u64 A = __ldg(ep + t);
        u64 B = __ldg(el + t);
        sep[t] = A;
        slb[t] = B;
        sb = __popcll(A & B);
        #pragma unroll
        for (int o = 16; o; o >>= 1) sb += __shfl_down_sync(0xffffffffu, sb, o);
        if ((t & 31) == 0) ssb[t >> 5] = sb;
    }
    __syncthreads();
    const int bit   = t >> 4;    // 0..63
    const int chunk = t & 15;    // strided row subset
    int n1p = 0, selc = 0;
    #pragma unroll
    for (int i = 0; i < 32; ++i) {
        int h = chunk + 16*i;    // lanes 0-15 hit 16 consecutive u64s: no conflicts
        n1p  += (int)((sep[h] >> bit) & 1ull);
        selc += (int)((slb[h] >> bit) & 1ull);
    }
    // combine 16 row-chunks of the same bit (adjacent lanes)
    #pragma unroll
    for (int o = 8; o; o >>= 1) {
        n1p  += __shfl_down_sync(0xffffffffu, n1p,  o, 16);
        selc += __shfl_down_sync(0xffffffffu, selc, o, 16);
    }
    float val = 0.0f;
    if (chunk == 0) {
        const float EM1 = 1.7182818284590452f;    // e - 1
        float lse = logf(512.0f + (float)n1p * EM1);
        val = (float)selc * lse;
    }
    // warp + block reduce, one atomic per block
    #pragma unroll
    for (int o = 16; o; o >>= 1) val += __shfl_down_sync(0xffffffffu, val, o);
    __shared__ float wsum[32];
    if ((t & 31) == 0) wsum[t >> 5] = val;
    __syncthreads();
    if (t < 32) {
        float v = wsum[t];
        #pragma unroll
        for (int o = 16; o; o >>= 1) v += __shfl_down_sync(0xffffffffu, v, o);
        if (t == 0) {
            int stot = 0;
            #pragma unroll
            for (int i = 0; i < 16; ++i) stot += ssb[i];
            atomicAdd(&g_loss, (v - (float)stot) * (1.0f/4096.0f));
        }
    }
    // last block finalizes the scalar output
    if (t == 0) {
        __threadfence();
        unsigned prev = atomicAdd(&g_count, 1u);
        if (prev == gridDim.x - 1) {
            out[0] = atomicAdd(&g_loss, 0.0f);  // atomic read: coherent with adds
        }
    }
}

// ---------------------------------------------------------------------------
extern "C" void kernel_launch(void* const* d_in, const int* in_sizes, int n_in,
                              void* d_out, int out_size) {
    const float* pred   = (const float*)d_in[0];
    const float* labels = (const float*)d_in[1];
    // defensive: identify by size (pred has 19x more elements)
    if (n_in >= 2 && in_sizes[0] == BATCH*HH*WW) {
        const float* tmp = pred; pred = labels; labels = tmp;
    }

    // one-time host-side setup (streams/events are host objects, not device mem)
    static cudaStream_t s2 = nullptr;
    static cudaEvent_t evFork = nullptr, evJoin = nullptr;
    static bool smem_set = false;
    if (!s2) {
        cudaStreamCreateWithFlags(&s2, cudaStreamNonBlocking);
        cudaEventCreateWithFlags(&evFork, cudaEventDisableTiming);
        cudaEventCreateWithFlags(&evJoin, cudaEventDisableTiming);
    }
    if (!smem_set) {
        cudaFuncSetAttribute(hyst_kernel<0>, cudaFuncAttributeMaxDynamicSharedMemorySize,
                             2*IMG_WORDS*(int)sizeof(u64));
        cudaFuncSetAttribute(hyst_kernel<1>, cudaFuncAttributeMaxDynamicSharedMemorySize,
                             2*IMG_WORDS*(int)sizeof(u64));
        smem_set = true;
    }

    dim3 g(WW/64, HH/64, BATCH);

    // fork: label pipeline on s2 (independent of argmax)
    cudaEventRecord(evFork, 0);
    cudaStreamWaitEvent(s2, evFork, 0);
    canny_front<1><<<g, 256, 0, s2>>>(labels);
    hyst_kernel<1><<<BATCH, 512, 2*IMG_WORDS*sizeof(u64), s2>>>();
    cudaEventRecord(evJoin, s2);

    // pred pipeline on default stream
    argmax_kernel<<<(BATCH*((HH*WW)/4)/2)/256, 256>>>(pred);
    canny_front<0><<<g, 256>>>(nullptr);
    hyst_kernel<0><<<BATCH, 512, 2*IMG_WORDS*sizeof(u64)>>>();

    // join, then loss
    cudaStreamWaitEvent(0, evJoin, 0);
    loss_kernel<<<64, 1024>>>((float*)d_out);
}